// round 8
// baseline (speedup 1.0000x reference)
#include <cuda_runtime.h>
#include <math.h>
#include <stdint.h>

#define N_CELLS 20
#define IN 8
#define HID 10
#define NGATES 800
#define FEAT 200
#define H1 50
#define H2 10

#define PITCH_IH 9     // odd pitch, coprime to 32
#define PITCH_HH 11    // odd pitch, coprime to 32

// Dynamic shared layout (float offsets). Keep FEAT/H0/W2 16B-aligned (mult of 4).
#define OFF_WIH   0
#define OFF_WHH   (OFF_WIH + NGATES * PITCH_IH)    // 7200
#define OFF_X     (OFF_WHH + NGATES * PITCH_HH)    // 16000
#define OFF_H0    (OFF_X + IN)                     // 16008
#define OFF_FEAT  (OFF_H0 + FEAT)                  // 16208 (mult of 4: OK)
#define OFF_H1    (OFF_FEAT + FEAT)                // 16408
#define OFF_W2    (OFF_H1 + H1 + 2)                // 16460 (mult of 4: OK)
#define SMEM_FLOATS (OFF_W2 + H2 * H1)             // 16960
#define SMEM_BYTES  (SMEM_FLOATS * 4)              // 67840

__device__ __forceinline__ float tanh_fast(float x) {
    float xc = fminf(fmaxf(x, -15.0f), 15.0f);
    float e = __expf(2.0f * xc);
    return __fdividef(e - 1.0f, e + 1.0f);
}
__device__ __forceinline__ float sigmoid_fast(float x) {
    float xc = fminf(fmaxf(x, -30.0f), 30.0f);
    return __fdividef(1.0f, 1.0f + __expf(-xc));
}

template <bool VEC>
__global__ __launch_bounds__(800, 1)
void lstm_mlp_fused(const float* __restrict__ x,
                    const float* __restrict__ h0,
                    const float* __restrict__ c0,
                    const float* __restrict__ W_ih,
                    const float* __restrict__ W_hh,
                    const float* __restrict__ b_ih,
                    const float* __restrict__ b_hh,
                    const float* __restrict__ W1,
                    const float* __restrict__ b1,
                    const float* __restrict__ W2,
                    const float* __restrict__ b2,
                    const float* __restrict__ W3,
                    const float* __restrict__ b3,
                    float* __restrict__ out)
{
    extern __shared__ float sm[];
    const int t = threadIdx.x;
    const int lane   = t & 31;
    const int lane16 = t & 15;
    const int row16  = t >> 4;                 // stage-3 row 0..49

    // Merged stage-1+2 mapping: warp w owns outputs o=8w..8w+7;
    // lane = 4q+g computes gate g of output o=8w+q.
    const int o    = (t >> 5) * 8 + (lane >> 2);   // 0..199
    const int g    = lane & 3;
    const int cell = o / 10;
    const int j    = o - cell * 10;
    const int r    = cell * 40 + g * 10 + j;       // gate row 0..799

    // ================= Entry: global -> shared / registers ===================
    float bias = b_ih[r] + b_hh[r];
    float c0r  = c0[o];

    if (VEC) {
        // W_ih: 1600 float4, 2 per thread, scatter to pitch-9 rows
        const float4* a4 = (const float4*)W_ih;
        #pragma unroll
        for (int k = 0; k < 2; ++k) {
            int idx = t + 800 * k;                 // < 1600
            float4 v = a4[idx];
            int e = idx * 4;                       // e%8 is 0 or 4
            float* dst = sm + OFF_WIH + (e >> 3) * PITCH_IH + (e & 7);
            dst[0] = v.x; dst[1] = v.y; dst[2] = v.z; dst[3] = v.w;
        }
        // W_hh: 2000 float4, 2.5 per thread
        const float4* b4 = (const float4*)W_hh;
        #pragma unroll
        for (int k = 0; k < 2; ++k) {
            int idx = t + 800 * k;                 // < 1600
            float4 v = b4[idx];
            int e = idx * 4;
            sm[OFF_WHH + (e / HID) * PITCH_HH + (e % HID)]         = v.x;
            sm[OFF_WHH + ((e+1) / HID) * PITCH_HH + ((e+1) % HID)] = v.y;
            sm[OFF_WHH + ((e+2) / HID) * PITCH_HH + ((e+2) % HID)] = v.z;
            sm[OFF_WHH + ((e+3) / HID) * PITCH_HH + ((e+3) % HID)] = v.w;
        }
        if (t < 400) {
            int idx = 1600 + t;
            float4 v = b4[idx];
            int e = idx * 4;
            sm[OFF_WHH + (e / HID) * PITCH_HH + (e % HID)]         = v.x;
            sm[OFF_WHH + ((e+1) / HID) * PITCH_HH + ((e+1) % HID)] = v.y;
            sm[OFF_WHH + ((e+2) / HID) * PITCH_HH + ((e+2) % HID)] = v.z;
            sm[OFF_WHH + ((e+3) / HID) * PITCH_HH + ((e+3) % HID)] = v.w;
        }
        // W2 -> shared, float4 (500 floats = 125 float4)
        if (t < 125) ((float4*)(sm + OFF_W2))[t] = ((const float4*)W2)[t];
        // h0 -> shared, float4
        if (t >= 128 && t < 178)
            ((float4*)(sm + OFF_H0))[t - 128] = ((const float4*)h0)[t - 128];
    } else {
        #pragma unroll
        for (int k = 0; k < 8; ++k) {
            int q = t + 800 * k;
            sm[OFF_WIH + (q >> 3) * PITCH_IH + (q & 7)] = W_ih[q];
        }
        #pragma unroll
        for (int k = 0; k < 10; ++k) {
            int q = t + 800 * k;
            sm[OFF_WHH + (q / HID) * PITCH_HH + (q % HID)] = W_hh[q];
        }
        if (t < H2 * H1) sm[OFF_W2 + t] = W2[t];
        if (t < FEAT)    sm[OFF_H0 + t] = h0[t];
    }

    // Stage-3 W1 row slice in registers (16 lanes per row)
    float4 w1q[3];
    float  w1r[12];
    float  w1t;
    if (VEC) {
        const float4* w4p = (const float4*)(W1 + row16 * FEAT);  // 200*4B: 16B mult
        #pragma unroll
        for (int u = 0; u < 3; ++u) w1q[u] = w4p[lane16 + (u << 4)];
        float4 tv = (lane16 < 2) ? w4p[48 + lane16]
                                 : make_float4(0.f, 0.f, 0.f, 0.f);
        w1q[0].x = w1q[0].x; // keep
        // stash tail in w1r[0..3] slot-free: reuse w1t trick below
        w1r[0] = tv.x; w1r[1] = tv.y; w1r[2] = tv.z; w1r[3] = tv.w;
        w1t = 0.0f;
    } else {
        const float* w1p = W1 + row16 * FEAT + lane16;
        #pragma unroll
        for (int u = 0; u < 12; ++u) w1r[u] = w1p[u << 4];
        w1t = (lane16 < 8) ? w1p[192] : 0.0f;
    }
    float b1r = (lane16 == 0) ? b1[row16] : 0.0f;

    // Stage-4/5 operands (warp 0 only)
    float b2r = 0.0f, w3r = 0.0f, b3r = 0.0f;
    if (t < H2) { b2r = b2[t]; w3r = W3[t]; }
    if (t == 0) b3r = b3[0];

    if (t < IN) sm[OFF_X + t] = x[t];
    __syncthreads();

    // ======== Stage 1+2 merged: gate dot + activation + cell update ==========
    {
        const float* wi = sm + OFF_WIH + r * PITCH_IH;
        const float* wh = sm + OFF_WHH + r * PITCH_HH;
        const float* xx = sm + OFF_X;
        const float* hr = sm + OFF_H0 + cell * HID;
        float acc = bias;
        #pragma unroll
        for (int i = 0; i < IN; ++i)  acc = fmaf(wi[i], xx[i], acc);
        #pragma unroll
        for (int k = 0; k < HID; ++k) acc = fmaf(wh[k], hr[k], acc);

        float vin = (g == 2) ? (acc + acc) : acc;
        float s   = sigmoid_fast(vin);
        float act = (g == 2) ? fmaf(2.0f, s, -1.0f) : s;

        const int base = lane & ~3;
        float ia = __shfl_sync(0xffffffffu, act, base);
        float fa = __shfl_sync(0xffffffffu, act, base + 1);
        float ga = __shfl_sync(0xffffffffu, act, base + 2);
        float oa = __shfl_sync(0xffffffffu, act, base + 3);
        if (g == 0) {
            float c = fmaf(fa, c0r, ia * ga);
            float h = oa * tanh_fast(c);
            int fidx = (cell >= 10) ? (o - 100) : (o + 100);
            sm[OFF_FEAT + fidx] = h;
        }
    }
    __syncthreads();

    // ======== Stage 3: h1 = tanh(W1 @ feat + b1), 16 lanes/row ===============
    {
        float sum = 0.0f;
        if (VEC) {
            const float4* f4 = (const float4*)(sm + OFF_FEAT);
            #pragma unroll
            for (int u = 0; u < 3; ++u) {
                float4 f = f4[lane16 + (u << 4)];
                float4 w = w1q[u];
                sum = fmaf(w.x, f.x, sum);
                sum = fmaf(w.y, f.y, sum);
                sum = fmaf(w.z, f.z, sum);
                sum = fmaf(w.w, f.w, sum);
            }
            if (lane16 < 2) {
                float4 f = f4[48 + lane16];
                sum = fmaf(w1r[0], f.x, sum);
                sum = fmaf(w1r[1], f.y, sum);
                sum = fmaf(w1r[2], f.z, sum);
                sum = fmaf(w1r[3], f.w, sum);
            }
        } else {
            const float* f = sm + OFF_FEAT;
            #pragma unroll
            for (int u = 0; u < 12; ++u)
                sum = fmaf(w1r[u], f[lane16 + (u << 4)], sum);
            if (lane16 < 8)
                sum = fmaf(w1t, f[192 + lane16], sum);
        }
        sum += __shfl_xor_sync(0xffffffffu, sum, 8);
        sum += __shfl_xor_sync(0xffffffffu, sum, 4);
        sum += __shfl_xor_sync(0xffffffffu, sum, 2);
        sum += __shfl_xor_sync(0xffffffffu, sum, 1);
        if (lane16 == 0) sm[OFF_H1 + row16] = tanh_fast(sum + b1r);
    }
    __syncthreads();

    // ======== Stage 4+5 fused in warp 0 ======================================
    if (t < 32) {
        float sum = 0.0f;
        if (t < H2) {
            const float* wv = sm + OFF_W2 + t * H1;
            const float* hv = sm + OFF_H1;
            #pragma unroll
            for (int i = 0; i < H1; ++i) sum = fmaf(wv[i], hv[i], sum);
        }
        float p = (t < H2) ? w3r * tanh_fast(sum + b2r) : 0.0f;
        #pragma unroll
        for (int m = 16; m > 0; m >>= 1)
            p += __shfl_xor_sync(0xffffffffu, p, m);
        if (t == 0) out[0] = tanh_fast(p + b3r);
    }
}

static inline bool aligned16(const void* p) {
    return (((uintptr_t)p) & 15u) == 0;
}

extern "C" void kernel_launch(void* const* d_in, const int* in_sizes, int n_in,
                              void* d_out, int out_size) {
    (void)in_sizes; (void)n_in; (void)out_size;
    const float* x    = (const float*)d_in[0];
    const float* h0   = (const float*)d_in[1];
    const float* c0   = (const float*)d_in[2];
    const float* W_ih = (const float*)d_in[3];
    const float* W_hh = (const float*)d_in[4];
    const float* b_ih = (const float*)d_in[5];
    const float* b_hh = (const float*)d_in[6];
    const float* W1   = (const float*)d_in[7];
    const float* b1   = (const float*)d_in[8];
    const float* W2   = (const float*)d_in[9];
    const float* b2   = (const float*)d_in[10];
    const float* W3   = (const float*)d_in[11];
    const float* b3   = (const float*)d_in[12];
    float* out = (float*)d_out;

    static bool attr_set = false;
    if (!attr_set) {
        cudaFuncSetAttribute(lstm_mlp_fused<true>,
                             cudaFuncAttributeMaxDynamicSharedMemorySize,
                             SMEM_BYTES);
        cudaFuncSetAttribute(lstm_mlp_fused<false>,
                             cudaFuncAttributeMaxDynamicSharedMemorySize,
                             SMEM_BYTES);
        attr_set = true;
    }

    const bool vec = aligned16(W_ih) && aligned16(W_hh) && aligned16(W1) &&
                     aligned16(h0) && aligned16(W2);

    if (vec) {
        lstm_mlp_fused<true><<<1, 800, SMEM_BYTES>>>(
            x, h0, c0, W_ih, W_hh, b_ih, b_hh, W1, b1, W2, b2, W3, b3, out);
    } else {
        lstm_mlp_fused<false><<<1, 800, SMEM_BYTES>>>(
            x, h0, c0, W_ih, W_hh, b_ih, b_hh, W1, b1, W2, b2, W3, b3, out);
    }
}

// round 9
// speedup vs baseline: 1.0295x; 1.0295x over previous
#include <cuda_runtime.h>
#include <math.h>
#include <stdint.h>

#define IN 8
#define HID 10
#define FEAT 200
#define H1 50
#define H2 10

#define PITCH_IH 9      // coprime to 32: conflict-free LDS rows
#define PITCH_HH 11
#define ROWS_LOC 400    // gate rows per CTA (10 cells * 40)

// Per-CTA dynamic shared layout (float offsets)
#define OFF_WIH   0
#define OFF_WHH   (OFF_WIH + ROWS_LOC * PITCH_IH)   // 3600
#define OFF_X     (OFF_WHH + ROWS_LOC * PITCH_HH)   // 8000
#define OFF_H0    (OFF_X + IN)                      // 8008
#define OFF_FEAT  (OFF_H0 + 100)                    // 8108
#define OFF_H1    (OFF_FEAT + FEAT)                 // 8308
#define OFF_W2    (OFF_H1 + H1)                     // 8358
#define SMEM_FLOATS (OFF_W2 + H2 * H1)              // 8858
#define SMEM_BYTES  (SMEM_FLOATS * 4)               // 35432

__device__ __forceinline__ float tanh_fast(float x) {
    float xc = fminf(fmaxf(x, -15.0f), 15.0f);
    float e = __expf(2.0f * xc);
    return __fdividef(e - 1.0f, e + 1.0f);
}
__device__ __forceinline__ float sigmoid_fast(float x) {
    float xc = fminf(fmaxf(x, -30.0f), 30.0f);
    return __fdividef(1.0f, 1.0f + __expf(-xc));
}
__device__ __forceinline__ uint32_t smem_u32(const void* p) {
    return (uint32_t)__cvta_generic_to_shared(p);
}
// Store 4 bytes into the peer CTA's shared memory at the same offset.
__device__ __forceinline__ void st_peer(uint32_t laddr, uint32_t peer, float v) {
    uint32_t rem;
    asm volatile("mapa.shared::cluster.u32 %0, %1, %2;"
                 : "=r"(rem) : "r"(laddr), "r"(peer));
    asm volatile("st.shared::cluster.u32 [%0], %1;"
                 :: "r"(rem), "r"(__float_as_uint(v)) : "memory");
}
__device__ __forceinline__ void cluster_sync_() {
    asm volatile("barrier.cluster.arrive.aligned;" ::: "memory");
    asm volatile("barrier.cluster.wait.aligned;" ::: "memory");
}

__global__ __launch_bounds__(800, 1) __cluster_dims__(2, 1, 1)
void lstm_mlp_cluster(const float* __restrict__ x,
                      const float* __restrict__ h0,
                      const float* __restrict__ c0,
                      const float* __restrict__ W_ih,
                      const float* __restrict__ W_hh,
                      const float* __restrict__ b_ih,
                      const float* __restrict__ b_hh,
                      const float* __restrict__ W1,
                      const float* __restrict__ b1,
                      const float* __restrict__ W2,
                      const float* __restrict__ b2,
                      const float* __restrict__ W3,
                      const float* __restrict__ b3,
                      float* __restrict__ out)
{
    extern __shared__ float sm[];
    const int t = threadIdx.x;
    const int lane = t & 31;
    uint32_t rank;
    asm("mov.u32 %0, %%cluster_ctarank;" : "=r"(rank));
    const uint32_t peer = rank ^ 1u;

    // ---- Stage-1 mapping (warps 0..12): lane = 4q+g computes gate g of
    // local output o = 8*warp + q; o in 0..103, valid o < 100.
    const int o = (t >> 5) * 8 + (lane >> 2);
    const int g = lane & 3;
    const int oc = (o < 100) ? o : 99;           // clamp for safe reads
    const int cl = oc / 10;
    const int jj = oc - cl * 10;
    const int lr = cl * 40 + g * 10 + jj;        // local gate row 0..399

    // ---- Stage-3 mapping (warps 0..12): 16 lanes per h1 row, 25 rows/CTA
    const int lane16 = t & 15;
    const int row_raw = t >> 4;                  // 0..49 over t<800
    const int row_loc = (row_raw < 25) ? row_raw : 24;  // clamp (warp 12 tail)
    const int row_glb = 25 * (int)rank + row_loc;

    // ================= Entry: stage this CTA's half =================
    // W_ih half: 3200 floats, 4 per thread, coalesced LDG -> pitch-9 rows
    const float* wihg = W_ih + rank * (ROWS_LOC * IN);
    #pragma unroll
    for (int k = 0; k < 4; ++k) {
        int q = t + 800 * k;
        sm[OFF_WIH + (q >> 3) * PITCH_IH + (q & 7)] = wihg[q];
    }
    // W_hh half: 4000 floats, 5 per thread
    const float* whhg = W_hh + rank * (ROWS_LOC * HID);
    #pragma unroll
    for (int k = 0; k < 5; ++k) {
        int q = t + 800 * k;
        sm[OFF_WHH + (q / HID) * PITCH_HH + (q % HID)] = whhg[q];
    }

    // Stage-1 per-thread operands
    float bias = 0.0f, c0r = 0.0f;
    if (t < 416) {
        int gr = (int)rank * ROWS_LOC + lr;
        bias = b_ih[gr] + b_hh[gr];
        if (o < 100) c0r = c0[(int)rank * 100 + o];
    }

    // Stage-3 operands: W1 row slice in registers (16 lanes/row)
    float w1r[12], w1t = 0.0f, b1r = 0.0f;
    if (t < 416) {
        const float* w1p = W1 + row_glb * FEAT + lane16;
        #pragma unroll
        for (int u = 0; u < 12; ++u) w1r[u] = w1p[u << 4];
        w1t = (lane16 < 8) ? w1p[192] : 0.0f;
        b1r = (lane16 == 0) ? b1[row_glb] : 0.0f;
    }

    // Stage-4/5 operands + W2 staging (CTA 0 only)
    float b2r = 0.0f, w3r = 0.0f, b3r = 0.0f;
    if (rank == 0) {
        if (t < H2 * H1) sm[OFF_W2 + t] = W2[t];
        if (t < H2) { b2r = b2[t]; w3r = W3[t]; }
        if (t == 0) b3r = b3[0];
    }

    // Small vectors
    if (t < 100) sm[OFF_H0 + t] = h0[(int)rank * 100 + t];
    if (t >= 128 && t < 128 + IN) sm[OFF_X + (t - 128)] = x[t - 128];
    __syncthreads();   // weights are CTA-local: local barrier suffices

    // ======== Stage 1+2: gate dots + activations + cell update ========
    if (t < 416) {
        const float* wi = sm + OFF_WIH + lr * PITCH_IH;
        const float* wh = sm + OFF_WHH + lr * PITCH_HH;
        const float* xx = sm + OFF_X;
        const float* hr = sm + OFF_H0 + cl * HID;
        float acc = bias;
        #pragma unroll
        for (int i = 0; i < IN; ++i)  acc = fmaf(wi[i], xx[i], acc);
        #pragma unroll
        for (int k = 0; k < HID; ++k) acc = fmaf(wh[k], hr[k], acc);

        float vin = (g == 2) ? (acc + acc) : acc;     // tanh = 2*sig(2x)-1
        float s   = sigmoid_fast(vin);
        float act = (g == 2) ? fmaf(2.0f, s, -1.0f) : s;

        const int base = lane & ~3;
        float ia = __shfl_sync(0xffffffffu, act, base);
        float fa = __shfl_sync(0xffffffffu, act, base + 1);
        float ga = __shfl_sync(0xffffffffu, act, base + 2);
        float oa = __shfl_sync(0xffffffffu, act, base + 3);
        if (g == 0 && o < 100) {
            float c = fmaf(fa, c0r, ia * ga);
            float h = oa * tanh_fast(c);
            // gen bank (cells 10-19 = rank 1) occupies feat[0..99]
            int fidx = (rank == 1) ? o : (100 + o);
            float* dst = sm + OFF_FEAT + fidx;
            *dst = h;
            st_peer(smem_u32(dst), peer, h);
        }
    }
    cluster_sync_();   // full feat visible in both CTAs

    // ======== Stage 3: 25 h1 rows per CTA, 16 lanes/row ========
    if (t < 416) {
        const float* f = sm + OFF_FEAT;
        float sum = 0.0f;
        #pragma unroll
        for (int u = 0; u < 12; ++u)
            sum = fmaf(w1r[u], f[lane16 + (u << 4)], sum);
        if (lane16 < 8)
            sum = fmaf(w1t, f[192 + lane16], sum);
        sum += __shfl_xor_sync(0xffffffffu, sum, 8);
        sum += __shfl_xor_sync(0xffffffffu, sum, 4);
        sum += __shfl_xor_sync(0xffffffffu, sum, 2);
        sum += __shfl_xor_sync(0xffffffffu, sum, 1);
        if (lane16 == 0 && row_raw < 25) {
            float v = tanh_fast(sum + b1r);
            if (rank == 0) {
                sm[OFF_H1 + row_glb] = v;
            } else {
                // deliver to CTA0's h1
                st_peer(smem_u32(sm + OFF_H1 + row_glb), 0u, v);
            }
        }
    }
    cluster_sync_();   // CTA0 has all 50 h1 values; CTA1 may exit after

    // ======== Stage 4+5 (CTA0, warp 0): h2 rows per lane + reduce ========
    if (rank == 0 && t < 32) {
        float sum = 0.0f;
        if (t < H2) {
            const float* wv = sm + OFF_W2 + t * H1;   // banks 18r mod 32 distinct
            const float* hv = sm + OFF_H1;            // broadcast reads
            #pragma unroll
            for (int i = 0; i < H1; ++i) sum = fmaf(wv[i], hv[i], sum);
        }
        float p = (t < H2) ? w3r * tanh_fast(sum + b2r) : 0.0f;
        #pragma unroll
        for (int m = 16; m > 0; m >>= 1)
            p += __shfl_xor_sync(0xffffffffu, p, m);
        if (t == 0) out[0] = tanh_fast(p + b3r);
    }
}

extern "C" void kernel_launch(void* const* d_in, const int* in_sizes, int n_in,
                              void* d_out, int out_size) {
    (void)in_sizes; (void)n_in; (void)out_size;
    const float* x    = (const float*)d_in[0];
    const float* h0   = (const float*)d_in[1];
    const float* c0   = (const float*)d_in[2];
    const float* W_ih = (const float*)d_in[3];
    const float* W_hh = (const float*)d_in[4];
    const float* b_ih = (const float*)d_in[5];
    const float* b_hh = (const float*)d_in[6];
    const float* W1   = (const float*)d_in[7];
    const float* b1   = (const float*)d_in[8];
    const float* W2   = (const float*)d_in[9];
    const float* b2   = (const float*)d_in[10];
    const float* W3   = (const float*)d_in[11];
    const float* b3   = (const float*)d_in[12];
    float* out = (float*)d_out;

    static bool attr_set = false;
    if (!attr_set) {
        cudaFuncSetAttribute(lstm_mlp_cluster,
                             cudaFuncAttributeMaxDynamicSharedMemorySize,
                             SMEM_BYTES);
        attr_set = true;
    }

    lstm_mlp_cluster<<<2, 800, SMEM_BYTES>>>(x, h0, c0, W_ih, W_hh, b_ih, b_hh,
                                             W1, b1, W2, b2, W3, b3, out);
}